// round 3
// baseline (speedup 1.0000x reference)
#include <cuda_runtime.h>

#define FIN 512
#define HID 16
#define CO  7
#define NMAX 200000

// Scratch (no allocations allowed -> __device__ globals)
__device__ float g_deg [NMAX];
__device__ float g_dinv[NMAX];
__device__ float g_g1  [NMAX * HID];   // (x@W1) * dinv[row]
__device__ float g_t1  [NMAX * HID];   // scatter-add accumulator, layer 1
__device__ float g_g2  [NMAX * 8];     // (relu(out1)@W2) * dinv[row], padded to 8
__device__ float g_t2  [NMAX * 8];     // scatter-add accumulator, layer 2

// ---------- helpers ----------
__device__ __forceinline__ void red4(float* p, float4 v) {
    asm volatile("red.global.add.v4.f32 [%0], {%1,%2,%3,%4};"
                 :: "l"(p), "f"(v.x), "f"(v.y), "f"(v.z), "f"(v.w) : "memory");
}
__device__ __forceinline__ void red1(float* p, float v) {
    asm volatile("red.global.add.f32 [%0], %1;" :: "l"(p), "f"(v) : "memory");
}
__device__ __forceinline__ unsigned long long fma2(unsigned long long a,
                                                   unsigned long long b,
                                                   unsigned long long c) {
    unsigned long long d;
    asm("fma.rn.f32x2 %0, %1, %2, %3;" : "=l"(d) : "l"(a), "l"(b), "l"(c));
    return d;
}
__device__ __forceinline__ unsigned long long pack2(float v) {
    unsigned long long r;
    asm("mov.b64 %0, {%1, %1};" : "=l"(r) : "f"(v));
    return r;
}
__device__ __forceinline__ float lo32(unsigned long long v) {
    return __uint_as_float((unsigned)(v & 0xffffffffull));
}
__device__ __forceinline__ float hi32(unsigned long long v) {
    return __uint_as_float((unsigned)(v >> 32));
}

// ---------- kernels ----------
// zero accumulators, deg = 1 (self loop)
__global__ void k_init(int n) {
    int i = blockIdx.x * blockDim.x + threadIdx.x;
    int total = n * HID;
    if (i < total)  g_t1[i] = 0.0f;
    if (i < n * 8)  g_t2[i] = 0.0f;
    if (i < n)      g_deg[i] = 1.0f;
}

__global__ void k_deg(const int* __restrict__ dst, int E) {
    int i = blockIdx.x * blockDim.x + threadIdx.x;
    if (i < E) red1(&g_deg[dst[i]], 1.0f);
}

__global__ void k_dinv(int n) {
    int i = blockIdx.x * blockDim.x + threadIdx.x;
    if (i < n) g_dinv[i] = rsqrtf(g_deg[i]);   // deg >= 1 always
}

// g1[row] = (x[row] @ W1) * dinv[row].  4 rows/thread, packed f32x2 FMA.
#define RPT 4
__global__ void __launch_bounds__(256) k_xform(const float* __restrict__ x,
                                               const float* __restrict__ W1, int n) {
    __shared__ float Ws[FIN * HID];             // 32 KB, row-major [k][j]
    for (int i = threadIdx.x; i < FIN * HID / 4; i += blockDim.x)
        ((float4*)Ws)[i] = __ldg(&((const float4*)W1)[i]);
    __syncthreads();
    const unsigned long long* Ws2 = (const unsigned long long*)Ws;  // [k][pair]

    int t  = blockIdx.x * blockDim.x + threadIdx.x;
    int r0 = t * RPT;
    if (r0 >= n) return;

    unsigned long long acc[RPT][8];
#pragma unroll
    for (int r = 0; r < RPT; r++)
#pragma unroll
        for (int p = 0; p < 8; p++) acc[r][p] = 0ull;

    const float4* xr[RPT];
#pragma unroll
    for (int r = 0; r < RPT; r++)
        xr[r] = (const float4*)(x + (size_t)(r0 + r) * FIN);

    for (int kk = 0; kk < FIN / 4; kk++) {
        float4 xv[RPT];
#pragma unroll
        for (int r = 0; r < RPT; r++) xv[r] = __ldg(&xr[r][kk]);
#pragma unroll
        for (int c = 0; c < 4; c++) {
            int k = kk * 4 + c;
            unsigned long long w[8];
#pragma unroll
            for (int p = 0; p < 8; p++) w[p] = Ws2[k * 8 + p];  // uniform LDS.64 broadcast
#pragma unroll
            for (int r = 0; r < RPT; r++) {
                float xa[4];
                *(float4*)xa = xv[r];
                unsigned long long x2 = pack2(xa[c]);
#pragma unroll
                for (int p = 0; p < 8; p++) acc[r][p] = fma2(x2, w[p], acc[r][p]);
            }
        }
    }

#pragma unroll
    for (int r = 0; r < RPT; r++) {
        int row = r0 + r;
        if (row < n) {
            float d = g_dinv[row];
            float o[16];
#pragma unroll
            for (int p = 0; p < 8; p++) {
                o[2 * p]     = lo32(acc[r][p]) * d;
                o[2 * p + 1] = hi32(acc[r][p]) * d;
            }
            float4* dst4 = (float4*)&g_g1[(size_t)row * HID];
#pragma unroll
            for (int q = 0; q < 4; q++) dst4[q] = *(float4*)&o[4 * q];
        }
    }
}

// scatter-add g1[src] into t1[dst]
__global__ void k_agg1(const int* __restrict__ src, const int* __restrict__ dst, int E) {
    int i = blockIdx.x * blockDim.x + threadIdx.x;
    if (i >= E) return;
    int s = src[i], d = dst[i];
    const float4* gs = (const float4*)&g_g1[(size_t)s * HID];
    float* td = &g_t1[(size_t)d * HID];
    red4(td + 0,  __ldg(gs + 0));
    red4(td + 4,  __ldg(gs + 1));
    red4(td + 8,  __ldg(gs + 2));
    red4(td + 12, __ldg(gs + 3));
}

// out1 = relu(dinv*(t1 + g1) + b1);  g2 = (out1 @ W2) * dinv
__global__ void k_mid(const float* __restrict__ W2, const float* __restrict__ b1, int n) {
    int i = blockIdx.x * blockDim.x + threadIdx.x;
    if (i >= n) return;
    float d = g_dinv[i];
    float h[16];
#pragma unroll
    for (int q = 0; q < 4; q++) {
        float4 tv = *(const float4*)&g_t1[(size_t)i * HID + 4 * q];
        float4 gv = *(const float4*)&g_g1[(size_t)i * HID + 4 * q];
        h[4 * q + 0] = fmaxf(d * (tv.x + gv.x) + __ldg(&b1[4 * q + 0]), 0.0f);
        h[4 * q + 1] = fmaxf(d * (tv.y + gv.y) + __ldg(&b1[4 * q + 1]), 0.0f);
        h[4 * q + 2] = fmaxf(d * (tv.z + gv.z) + __ldg(&b1[4 * q + 2]), 0.0f);
        h[4 * q + 3] = fmaxf(d * (tv.w + gv.w) + __ldg(&b1[4 * q + 3]), 0.0f);
    }
    float o[CO];
#pragma unroll
    for (int j = 0; j < CO; j++) o[j] = 0.0f;
#pragma unroll
    for (int k = 0; k < HID; k++)
#pragma unroll
        for (int j = 0; j < CO; j++)
            o[j] = fmaf(h[k], __ldg(&W2[k * CO + j]), o[j]);
    float out8[8];
#pragma unroll
    for (int j = 0; j < CO; j++) out8[j] = o[j] * d;
    out8[7] = 0.0f;
    float4* dst4 = (float4*)&g_g2[(size_t)i * 8];
    dst4[0] = *(float4*)&out8[0];
    dst4[1] = *(float4*)&out8[4];
}

// scatter-add g2[src] into t2[dst]
__global__ void k_agg2(const int* __restrict__ src, const int* __restrict__ dst, int E) {
    int i = blockIdx.x * blockDim.x + threadIdx.x;
    if (i >= E) return;
    int s = src[i], d = dst[i];
    const float4* gs = (const float4*)&g_g2[(size_t)s * 8];
    float* td = &g_t2[(size_t)d * 8];
    red4(td + 0, __ldg(gs + 0));
    red4(td + 4, __ldg(gs + 1));
}

// out = dinv*(t2 + g2) + b2
__global__ void k_final(const float* __restrict__ b2, float* __restrict__ out, int n) {
    int i = blockIdx.x * blockDim.x + threadIdx.x;
    if (i >= n) return;
    float d = g_dinv[i];
#pragma unroll
    for (int j = 0; j < CO; j++)
        out[(size_t)i * CO + j] =
            d * (g_t2[(size_t)i * 8 + j] + g_g2[(size_t)i * 8 + j]) + __ldg(&b2[j]);
}

// ---------- launch ----------
extern "C" void kernel_launch(void* const* d_in, const int* in_sizes, int n_in,
                              void* d_out, int out_size) {
    const float* x  = (const float*)d_in[0];
    const int*   ei = (const int*)  d_in[1];
    const float* W1 = (const float*)d_in[2];
    const float* b1 = (const float*)d_in[3];
    const float* W2 = (const float*)d_in[4];
    const float* b2 = (const float*)d_in[5];

    int n = in_sizes[0] / FIN;
    int E = in_sizes[1] / 2;
    const int* src = ei;
    const int* dst = ei + E;

    const int TB = 256;
    int gInit  = (n * HID + TB - 1) / TB;
    int gEdge  = (E + TB - 1) / TB;
    int gNode  = (n + TB - 1) / TB;
    int gXform = ((n + RPT - 1) / RPT + TB - 1) / TB;

    k_init <<<gInit,  TB>>>(n);
    k_deg  <<<gEdge,  TB>>>(dst, E);
    k_dinv <<<gNode,  TB>>>(n);
    k_xform<<<gXform, TB>>>(x, W1, n);
    k_agg1 <<<gEdge,  TB>>>(src, dst, E);
    k_mid  <<<gNode,  TB>>>(W2, b1, n);
    k_agg2 <<<gEdge,  TB>>>(src, dst, E);
    k_final<<<gNode,  TB>>>(b2, (float*)d_out, n);
}